// round 15
// baseline (speedup 1.0000x reference)
#include <cuda_runtime.h>
#include <math.h>

#define NIN 14
#define HID 128
#define LAT 64
#define CBN 512
#define MAXN 131072

#define SQRT2_F 1.41421356237f

// ---------------- device scratch (static: no allocations allowed) ----------------
__device__ unsigned long long g_zbuf[(size_t)MAXN * 32];  // z as f32x2 pairs, 33.5MB
__device__ float g_table[CBN * 16];                       // precomputed decoder outputs
__device__ float g_cbnorm[CBN];                           // sum(c*c), XLA:GPU warp-tree order
__device__ int g_hist[CBN];
__device__ unsigned long long g_commit;                   // fixed-point sum of ||q-z||^2

// ---------------- packed f32x2 helpers ----------------
static __device__ __forceinline__ unsigned long long ffma2(unsigned long long a,
                                                           unsigned long long b,
                                                           unsigned long long c) {
    unsigned long long d;
    asm("fma.rn.f32x2 %0, %1, %2, %3;" : "=l"(d) : "l"(a), "l"(b), "l"(c));
    return d;
}
static __device__ __forceinline__ unsigned long long fadd2(unsigned long long a,
                                                           unsigned long long b) {
    unsigned long long d;
    asm("add.rn.f32x2 %0, %1, %2;" : "=l"(d) : "l"(a), "l"(b));
    return d;
}
static __device__ __forceinline__ unsigned long long pack2(float lo, float hi) {
    unsigned long long r;
    asm("mov.b64 %0, {%1, %2};" : "=l"(r) : "r"(__float_as_uint(lo)), "r"(__float_as_uint(hi)));
    return r;
}
static __device__ __forceinline__ float2 unpack2(unsigned long long v) {
    unsigned int lo, hi;
    asm("mov.b64 {%0, %1}, %2;" : "=r"(lo), "=r"(hi) : "l"(v));
    float2 r;
    r.x = __uint_as_float(lo);
    r.y = __uint_as_float(hi);
    return r;
}

// reference-style GELU: 0.5 * x * (1 + erf(x / sqrt(2)))
static __device__ __forceinline__ float gelu_ref(float v) {
    float e = erff(v / SQRT2_F);
    return (v * (e + 1.f)) * 0.5f;
}

// XLA:GPU row-reduction emulation for 64-wide sum-of-squares (bit-frozen from R7).
#define GPU_SUMSQ64(getv, result) do {                                        \
    float _a[32];                                                             \
    _Pragma("unroll") for (int _t = 0; _t < 32; _t++) {                       \
        float _v0 = getv(_t);                                                 \
        float _v1 = getv(_t + 32);                                            \
        _a[_t] = fmaf(_v1, _v1, _v0 * _v0);                                   \
    }                                                                         \
    _Pragma("unroll") for (int _o = 16; _o >= 1; _o >>= 1)                    \
    _Pragma("unroll") for (int _t = 0; _t < 16; _t++)                         \
        if (_t < _o) _a[_t] = _a[_t] + _a[_t + _o];                           \
    result = _a[0];                                                           \
} while (0)

// ---------------- kernel 0: zero the cross-launch scratch ----------------
__global__ void k_init() {
    int t = threadIdx.x;
    if (t < CBN) g_hist[t] = 0;
    if (t == 0) g_commit = 0ULL;
}

// ---------------- kernel 1: decoder table (unchanged, bit-frozen) ----------
__global__ __launch_bounds__(256) void k_dectab(
    const float* __restrict__ cb,
    const float* __restrict__ w1, const float* __restrict__ b1,
    const float* __restrict__ g1, const float* __restrict__ bt1,
    const float* __restrict__ w2, const float* __restrict__ b2)
{
    __shared__ float w1s[LAT * HID];
    __shared__ float w2s[HID * NIN];
    __shared__ float cbuf[8][LAT];
    __shared__ float gbuf[8][HID];
    int tid = threadIdx.x;
    for (int i = tid; i < LAT * HID; i += 256) w1s[i] = w1[i];
    for (int i = tid; i < HID * NIN; i += 256) w2s[i] = w2[i];
    __syncthreads();

    int lane = tid & 31, w = tid >> 5;
    int c = blockIdx.x * 8 + w;

    for (int d = lane; d < LAT; d += 32) cbuf[w][d] = __ldg(&cb[c * LAT + d]);
    __syncwarp();

    if (lane == 0) {
        float ns;
#define GETC(d) (cbuf[w][(d)])
        GPU_SUMSQ64(GETC, ns);
#undef GETC
        g_cbnorm[c] = ns;
    }

    float h[4];
#pragma unroll
    for (int u = 0; u < 4; u++) {
        int j = u * 32 + lane;
        float acc = 0.f;
        for (int d = 0; d < LAT; d++) acc = fmaf(cbuf[w][d], w1s[d * HID + j], acc);
        h[u] = acc + __ldg(&b1[j]);
    }
    float s = (h[0] + h[1]) + (h[2] + h[3]);
#pragma unroll
    for (int o = 16; o; o >>= 1) s += __shfl_xor_sync(~0u, s, o);
    float mean = s * (1.f / HID);
    float dv[4], s2 = 0.f;
#pragma unroll
    for (int u = 0; u < 4; u++) { dv[u] = h[u] - mean; float sq = dv[u] * dv[u]; s2 = s2 + sq; }
#pragma unroll
    for (int o = 16; o; o >>= 1) s2 += __shfl_xor_sync(~0u, s2, o);
    float var = s2 * (1.f / HID);
    float rstd = 1.f / sqrtf(var + 1e-5f);
#pragma unroll
    for (int u = 0; u < 4; u++) {
        int j = u * 32 + lane;
        float t = dv[u] * rstd;
        float t2 = t * __ldg(&g1[j]);
        float v = t2 + __ldg(&bt1[j]);
        gbuf[w][j] = gelu_ref(v);
    }
    __syncwarp();
    if (lane < NIN) {
        float acc = 0.f;
        for (int j = 0; j < HID; j++) acc = fmaf(gbuf[w][j], w2s[j * NIN + lane], acc);
        g_table[c * 16 + lane] = acc + __ldg(&b2[lane]);
    }
}

// ---------------- kernel 2: encoder (unchanged from R12, bit-frozen z) -------
__global__ __launch_bounds__(256) void k_enc(
    const float* __restrict__ x,
    const float* __restrict__ w1, const float* __restrict__ b1,
    const float* __restrict__ g1, const float* __restrict__ bt1,
    const float* __restrict__ w2, const float* __restrict__ b2, int N)
{
    extern __shared__ float esm[];
    float* w1s = esm;
    float* w2i = w1s + NIN * HID;
    float* gsf = w2i + HID * LAT;

    int tid = threadIdx.x;
    for (int i = tid; i < NIN * HID; i += 256) w1s[i] = w1[i];
    for (int i = tid; i < HID * LAT; i += 256) {
        int jp = i >> 7;
        int r = i & 127;
        int l = r >> 2;
        int comp = r & 3;
        int j = 2 * jp + (comp >> 1);
        int d = 2 * l + (comp & 1);
        w2i[i] = w2[j * LAT + d];
    }
    __syncthreads();

    int lane = tid & 31, w = tid >> 5;

    float b1v[4], g1v[4], btv[4];
#pragma unroll
    for (int u = 0; u < 4; u++) {
        int j = u * 32 + lane;
        b1v[u] = __ldg(&b1[j]);
        g1v[u] = __ldg(&g1[j]);
        btv[u] = __ldg(&bt1[j]);
    }
    unsigned long long b2p = pack2(__ldg(&b2[2 * lane]), __ldg(&b2[2 * lane + 1]));

    int gw = blockIdx.x * 8 + w;
    int nw = gridDim.x * 8;

    for (int t0 = gw * 8; t0 < N; t0 += nw * 8) {
#pragma unroll 1
        for (int m = 0; m < 8; m++) {
            int t = t0 + m;
            float gl0 = 0.f, gl1 = 0.f, gl2 = 0.f, gl3 = 0.f;
            if (t < N) {
                const float* xp = x + (size_t)t * NIN;
                float xv[NIN];
#pragma unroll
                for (int i = 0; i < NIN; i++) xv[i] = __ldg(&xp[i]);
                float h[4];
#pragma unroll
                for (int u = 0; u < 4; u++) {
                    float acc = 0.f;
#pragma unroll
                    for (int i = 0; i < NIN; i++) acc = fmaf(xv[i], w1s[i * HID + u * 32 + lane], acc);
                    h[u] = acc + b1v[u];
                }
                float s = (h[0] + h[1]) + (h[2] + h[3]);
#pragma unroll
                for (int o = 16; o; o >>= 1) s += __shfl_xor_sync(~0u, s, o);
                float mean = s * (1.f / HID);
                float dv[4], s2 = 0.f;
#pragma unroll
                for (int u = 0; u < 4; u++) { dv[u] = h[u] - mean; float sq = dv[u] * dv[u]; s2 = s2 + sq; }
#pragma unroll
                for (int o = 16; o; o >>= 1) s2 += __shfl_xor_sync(~0u, s2, o);
                float var = s2 * (1.f / HID);
                float rstd = 1.f / sqrtf(var + 1e-5f);
                float t1, t2, v;
                t1 = dv[0] * rstd; t2 = t1 * g1v[0]; v = t2 + btv[0]; gl0 = gelu_ref(v);
                t1 = dv[1] * rstd; t2 = t1 * g1v[1]; v = t2 + btv[1]; gl1 = gelu_ref(v);
                t1 = dv[2] * rstd; t2 = t1 * g1v[2]; v = t2 + btv[2]; gl2 = gelu_ref(v);
                t1 = dv[3] * rstd; t2 = t1 * g1v[3]; v = t2 + btv[3]; gl3 = gelu_ref(v);
            }
            float* gp = gsf + (w * 8 + m) * HID;
            gp[0 * 32 + lane] = gl0;
            gp[1 * 32 + lane] = gl1;
            gp[2 * 32 + lane] = gl2;
            gp[3 * 32 + lane] = gl3;
        }
        __syncwarp();

        unsigned long long acc[8];
#pragma unroll
        for (int m = 0; m < 8; m++) acc[m] = 0ULL;
        const float* g0 = gsf + (w * 8) * HID;
#pragma unroll 4
        for (int j = 0; j < HID; j += 2) {
            ulonglong2 wv = *(const ulonglong2*)&w2i[(j >> 1) * 128 + lane * 4];
#pragma unroll
            for (int m = 0; m < 8; m++) {
                float2 g2 = *(const float2*)&g0[m * HID + j];
                acc[m] = ffma2(pack2(g2.x, g2.x), wv.x, acc[m]);
                acc[m] = ffma2(pack2(g2.y, g2.y), wv.y, acc[m]);
            }
        }
        __syncwarp();
#pragma unroll
        for (int m = 0; m < 8; m++) {
            int t = t0 + m;
            if (t < N) g_zbuf[(size_t)t * 32 + lane] = fadd2(acc[m], b2p);
        }
    }
}

// ---------------- kernel 3: VQ — 448 threads, 2 tokens/thread, one pass ------
#define GZ_ARR(arr, d) (((d) & 1) ? __uint_as_float((unsigned int)((arr)[(d) >> 1] >> 32)) \
                                  : __uint_as_float((unsigned int)(arr)[(d) >> 1]))
#define GZ_A(d) GZ_ARR(z2a, d)
#define GZ_B(d) GZ_ARR(z2b, d)

// Rescue (bit-frozen from R7): reference-replica d2 + quantization-tie force.
#define RESCUE(GETV, BIDXVAR) do {                                            \
    float zz_;                                                                \
    GPU_SUMSQ64(GETV, zz_);                                                   \
    float bestr_ = 3.4e38f, bestr2_ = 3.4e38f;                                \
    int bir_ = 0, bir2_ = 0;                                                  \
    for (int c_ = 0; c_ < CBN; c_++) {                                        \
        const float* p_ = cbs + c_ * LAT;                                     \
        float a_ = 0.f;                                                       \
        _Pragma("unroll") for (int d_ = 0; d_ < LAT; d_++)                    \
            a_ = fmaf(GETV(d_), p_[d_], a_);                                  \
        float t0_ = zz_ - 2.f * a_;                                           \
        float sc_ = t0_ + cns[c_];                                            \
        if (sc_ < bestr_) { bestr2_ = bestr_; bir2_ = bir_; bestr_ = sc_; bir_ = c_; } \
        else if (sc_ < bestr2_) { bestr2_ = sc_; bir2_ = c_; }                \
    }                                                                         \
    BIDXVAR = bir_;                                                           \
    float win_ = fabsf(bestr_) * 2.4e-7f;                                     \
    if (bestr2_ - bestr_ <= win_ && bir2_ < bir_) BIDXVAR = bir2_;            \
} while (0)

#define EPILOGUE(ARR, BIDX, T) do {                                           \
    float d2_ = 0.f;                                                          \
    const float* cr_ = cbs + (BIDX) * LAT;                                    \
    _Pragma("unroll") for (int u_ = 0; u_ < 32; u_++) {                       \
        unsigned long long zz2_ = (ARR)[u_];                                  \
        float zl_ = __uint_as_float((unsigned int)zz2_);                      \
        float zh_ = __uint_as_float((unsigned int)(zz2_ >> 32));              \
        float dl_ = zl_ - cr_[2 * u_];                                        \
        float dh_ = zh_ - cr_[2 * u_ + 1];                                    \
        d2_ = fmaf(dl_, dl_, d2_);                                            \
        d2_ = fmaf(dh_, dh_, d2_);                                            \
    }                                                                         \
    atomicAdd(&hs[BIDX], 1);                                                  \
    atomicAdd(&csum, __float2ull_rn(d2_ * 4194304.f));                        \
    if (out_idx) out_idx[T] = (float)(BIDX);                                  \
    if (out_rec) {                                                            \
        float* orp_ = out_rec + (size_t)(T) * NIN;                            \
        const float* tb_ = g_table + (BIDX) * 16;                             \
        _Pragma("unroll") for (int i_ = 0; i_ < NIN; i_++)                    \
            orp_[i_] = __ldg(&tb_[i_]);                                       \
    }                                                                         \
} while (0)

__global__ __launch_bounds__(448, 1) void k_vq(
    const float* __restrict__ cb,
    float* __restrict__ out_rec, float* __restrict__ out_idx, int N)
{
    extern __shared__ float sm[];
    float* cbs = sm;                        // 512*64 floats = 128KB
    float* cns = sm + CBN * LAT;            // 512 floats
    int* hs = (int*)(cns + CBN);            // 512 ints
    __shared__ unsigned long long csum;

    int tid = threadIdx.x;
    for (int i = tid; i < CBN * LAT; i += 448) cbs[i] = cb[i];
    for (int i = tid; i < CBN; i += 448) { cns[i] = g_cbnorm[i]; hs[i] = 0; }
    if (tid == 0) csum = 0ULL;
    __syncthreads();

    // Single balanced pass: block covers 896 contiguous tokens.
    int ta = blockIdx.x * 896 + tid;
    int tb = ta + 448;
    bool va = ta < N, vb = tb < N;
    int la = va ? ta : 0;
    int lb = vb ? tb : la;

    unsigned long long z2a[32], z2b[32];
    {
        const ulonglong2* zp = (const ulonglong2*)&g_zbuf[(size_t)la * 32];
#pragma unroll
        for (int u = 0; u < 16; u++) {
            ulonglong2 v = zp[u];
            z2a[2 * u] = v.x;
            z2a[2 * u + 1] = v.y;
        }
    }
    {
        const ulonglong2* zp = (const ulonglong2*)&g_zbuf[(size_t)lb * 32];
#pragma unroll
        for (int u = 0; u < 16; u++) {
            ulonglong2 v = zp[u];
            z2b[2 * u] = v.x;
            z2b[2 * u + 1] = v.y;
        }
    }

    // ---- screen: eighth-granularity double-buffered prefetch, 2 tokens -------
    float bestA = 3.4e38f, best2A = 3.4e38f, bestB = 3.4e38f, best2B = 3.4e38f;
    int bidxA = 0, bidxB = 0;
    ulonglong2 e0[2], e1[2];
    {
        const ulonglong2* cp0 = (const ulonglong2*)cbs;
        e0[0] = cp0[0];
        e0[1] = cp0[1];
    }
#pragma unroll 1
    for (int c = 0; c < CBN; c++) {
        const ulonglong2* cp = (const ulonglong2*)(cbs + c * LAT);
        const ulonglong2* cpn = (const ulonglong2*)(cbs + ((c + 1) & (CBN - 1)) * LAT);
        unsigned long long aA0 = 0ULL, aA1 = 0ULL, aB0 = 0ULL, aB1 = 0ULL;
#pragma unroll
        for (int e = 0; e < 8; e++) {
            // prefetch next eighth (or next code's first eighth) into the spare buffer
            const ulonglong2* src = (e < 7) ? (cp + 2 * (e + 1)) : cpn;
            if ((e & 1) == 0) {
                e1[0] = src[0]; e1[1] = src[1];
                aA0 = ffma2(z2a[4 * e + 0], e0[0].x, aA0);
                aA1 = ffma2(z2a[4 * e + 1], e0[0].y, aA1);
                aA0 = ffma2(z2a[4 * e + 2], e0[1].x, aA0);
                aA1 = ffma2(z2a[4 * e + 3], e0[1].y, aA1);
                aB0 = ffma2(z2b[4 * e + 0], e0[0].x, aB0);
                aB1 = ffma2(z2b[4 * e + 1], e0[0].y, aB1);
                aB0 = ffma2(z2b[4 * e + 2], e0[1].x, aB0);
                aB1 = ffma2(z2b[4 * e + 3], e0[1].y, aB1);
            } else {
                e0[0] = src[0]; e0[1] = src[1];
                aA0 = ffma2(z2a[4 * e + 0], e1[0].x, aA0);
                aA1 = ffma2(z2a[4 * e + 1], e1[0].y, aA1);
                aA0 = ffma2(z2a[4 * e + 2], e1[1].x, aA0);
                aA1 = ffma2(z2a[4 * e + 3], e1[1].y, aA1);
                aB0 = ffma2(z2b[4 * e + 0], e1[0].x, aB0);
                aB1 = ffma2(z2b[4 * e + 1], e1[0].y, aB1);
                aB0 = ffma2(z2b[4 * e + 2], e1[1].x, aB0);
                aB1 = ffma2(z2b[4 * e + 3], e1[1].y, aB1);
            }
        }
        float cn = cns[c];
        float2 fA = unpack2(fadd2(aA0, aA1));
        float scoreA = fmaf(-2.f, fA.x + fA.y, cn);
        if (scoreA < bestA) { best2A = bestA; bestA = scoreA; bidxA = c; }
        else if (scoreA < best2A) { best2A = scoreA; }
        float2 fB = unpack2(fadd2(aB0, aB1));
        float scoreB = fmaf(-2.f, fB.x + fB.y, cn);
        if (scoreB < bestB) { best2B = bestB; bestB = scoreB; bidxB = c; }
        else if (scoreB < best2B) { best2B = scoreB; }
    }

    if (va) {
        if (best2A - bestA < 1e-4f) RESCUE(GZ_A, bidxA);
        EPILOGUE(z2a, bidxA, ta);
    }
    if (vb) {
        if (best2B - bestB < 1e-4f) RESCUE(GZ_B, bidxB);
        EPILOGUE(z2b, bidxB, tb);
    }

    __syncthreads();
    for (int i = tid; i < CBN; i += 448) {
        int v = hs[i];
        if (v) atomicAdd(&g_hist[i], v);
    }
    if (tid == 0) atomicAdd(&g_commit, csum);
}

// ---------------- kernel 4: finalize scalars ----------------
__global__ void k_fin(float* out_commit, float* out_perp, int N) {
    __shared__ float red[512];
    int tid = threadIdx.x;
    float p = (float)g_hist[tid] / (float)N;
    red[tid] = p * logf(p + 1e-10f);
    __syncthreads();
    for (int s = 256; s; s >>= 1) {
        if (tid < s) red[tid] += red[tid + s];
        __syncthreads();
    }
    if (tid == 0) {
        if (out_perp) *out_perp = expf(-red[0]);
        if (out_commit) {
            double sum = (double)g_commit * (1.0 / 4194304.0);
            *out_commit = (float)(0.25 * sum / ((double)N * 64.0));
        }
    }
}

// ---------------- launch ----------------
extern "C" void kernel_launch(void* const* d_in, const int* in_sizes, int n_in,
                              void* d_out, int out_size) {
    (void)n_in;
    const float* x   = (const float*)d_in[0];
    const float* ew1 = (const float*)d_in[1];
    const float* eb1 = (const float*)d_in[2];
    const float* l1g = (const float*)d_in[3];
    const float* l1b = (const float*)d_in[4];
    const float* ew2 = (const float*)d_in[5];
    const float* eb2 = (const float*)d_in[6];
    const float* cbk = (const float*)d_in[7];
    const float* dw1 = (const float*)d_in[8];
    const float* db1 = (const float*)d_in[9];
    const float* l2g = (const float*)d_in[10];
    const float* l2b = (const float*)d_in[11];
    const float* dw2 = (const float*)d_in[12];
    const float* db2 = (const float*)d_in[13];

    int N = in_sizes[0] / NIN;
    if (N > MAXN) N = MAXN;

    float* out = (float*)d_out;
    long long rec_n = (long long)N * NIN;
    long long osz = (long long)out_size;
    float* out_rec    = (osz >= rec_n)             ? out : nullptr;
    float* out_idx    = (osz >= rec_n + N)         ? out + rec_n : nullptr;
    float* out_commit = (osz >= rec_n + N + 1)     ? out + rec_n + N : nullptr;
    float* out_perp   = (osz >= rec_n + N + 2)     ? out + rec_n + N + 1 : nullptr;

    k_init<<<1, 512>>>();
    k_dectab<<<CBN / 8, 256>>>(cbk, dw1, db1, l2g, l2b, dw2, db2);

    int smem_enc = (NIN * HID + HID * LAT + 8 * 8 * HID) * 4;  // 72704 B
    cudaFuncSetAttribute(k_enc, cudaFuncAttributeMaxDynamicSharedMemorySize, smem_enc);
    k_enc<<<444, 256, smem_enc>>>(x, ew1, eb1, l1g, l1b, ew2, eb2, N);

    int smem = CBN * LAT * 4 + CBN * 4 + CBN * 4;  // 135168 B
    cudaFuncSetAttribute(k_vq, cudaFuncAttributeMaxDynamicSharedMemorySize, smem);
    int nblk = (N + 895) / 896;   // 147 blocks for N=131072, each 448 thr x 2 tokens
    k_vq<<<nblk, 448, smem>>>(cbk, out_rec, out_idx, N);

    k_fin<<<1, 512>>>(out_commit, out_perp, N);
}

// round 16
// speedup vs baseline: 1.2879x; 1.2879x over previous
#include <cuda_runtime.h>
#include <math.h>

#define NIN 14
#define HID 128
#define LAT 64
#define CBN 512
#define MAXN 131072

#define SQRT2_F 1.41421356237f

// ---------------- device scratch (static: no allocations allowed) ----------------
__device__ unsigned long long g_zbuf[(size_t)MAXN * 32];  // z as f32x2 pairs, 33.5MB
__device__ float g_table[CBN * 16];                       // precomputed decoder outputs
__device__ float g_cbnorm[CBN];                           // sum(c*c), XLA:GPU warp-tree order
__device__ int g_hist[CBN];
__device__ unsigned long long g_commit;                   // fixed-point sum of ||q-z||^2

// ---------------- packed f32x2 helpers ----------------
static __device__ __forceinline__ unsigned long long ffma2(unsigned long long a,
                                                           unsigned long long b,
                                                           unsigned long long c) {
    unsigned long long d;
    asm("fma.rn.f32x2 %0, %1, %2, %3;" : "=l"(d) : "l"(a), "l"(b), "l"(c));
    return d;
}
static __device__ __forceinline__ unsigned long long fadd2(unsigned long long a,
                                                           unsigned long long b) {
    unsigned long long d;
    asm("add.rn.f32x2 %0, %1, %2;" : "=l"(d) : "l"(a), "l"(b));
    return d;
}
static __device__ __forceinline__ unsigned long long pack2(float lo, float hi) {
    unsigned long long r;
    asm("mov.b64 %0, {%1, %2};" : "=l"(r) : "r"(__float_as_uint(lo)), "r"(__float_as_uint(hi)));
    return r;
}
static __device__ __forceinline__ float2 unpack2(unsigned long long v) {
    unsigned int lo, hi;
    asm("mov.b64 {%0, %1}, %2;" : "=r"(lo), "=r"(hi) : "l"(v));
    float2 r;
    r.x = __uint_as_float(lo);
    r.y = __uint_as_float(hi);
    return r;
}

// reference-style GELU: 0.5 * x * (1 + erf(x / sqrt(2)))
static __device__ __forceinline__ float gelu_ref(float v) {
    float e = erff(v / SQRT2_F);
    return (v * (e + 1.f)) * 0.5f;
}

// XLA:GPU row-reduction emulation for 64-wide sum-of-squares (bit-frozen from R7).
#define GPU_SUMSQ64(getv, result) do {                                        \
    float _a[32];                                                             \
    _Pragma("unroll") for (int _t = 0; _t < 32; _t++) {                       \
        float _v0 = getv(_t);                                                 \
        float _v1 = getv(_t + 32);                                            \
        _a[_t] = fmaf(_v1, _v1, _v0 * _v0);                                   \
    }                                                                         \
    _Pragma("unroll") for (int _o = 16; _o >= 1; _o >>= 1)                    \
    _Pragma("unroll") for (int _t = 0; _t < 16; _t++)                         \
        if (_t < _o) _a[_t] = _a[_t] + _a[_t + _o];                           \
    result = _a[0];                                                           \
} while (0)

// ---------------- kernel 0: zero the cross-launch scratch ----------------
__global__ void k_init() {
    int t = threadIdx.x;
    if (t < CBN) g_hist[t] = 0;
    if (t == 0) g_commit = 0ULL;
}

// ---------------- kernel 1: decoder table (unchanged, bit-frozen) ----------
__global__ __launch_bounds__(256) void k_dectab(
    const float* __restrict__ cb,
    const float* __restrict__ w1, const float* __restrict__ b1,
    const float* __restrict__ g1, const float* __restrict__ bt1,
    const float* __restrict__ w2, const float* __restrict__ b2)
{
    __shared__ float w1s[LAT * HID];
    __shared__ float w2s[HID * NIN];
    __shared__ float cbuf[8][LAT];
    __shared__ float gbuf[8][HID];
    int tid = threadIdx.x;
    for (int i = tid; i < LAT * HID; i += 256) w1s[i] = w1[i];
    for (int i = tid; i < HID * NIN; i += 256) w2s[i] = w2[i];
    __syncthreads();

    int lane = tid & 31, w = tid >> 5;
    int c = blockIdx.x * 8 + w;

    for (int d = lane; d < LAT; d += 32) cbuf[w][d] = __ldg(&cb[c * LAT + d]);
    __syncwarp();

    if (lane == 0) {
        float ns;
#define GETC(d) (cbuf[w][(d)])
        GPU_SUMSQ64(GETC, ns);
#undef GETC
        g_cbnorm[c] = ns;
    }

    float h[4];
#pragma unroll
    for (int u = 0; u < 4; u++) {
        int j = u * 32 + lane;
        float acc = 0.f;
        for (int d = 0; d < LAT; d++) acc = fmaf(cbuf[w][d], w1s[d * HID + j], acc);
        h[u] = acc + __ldg(&b1[j]);
    }
    float s = (h[0] + h[1]) + (h[2] + h[3]);
#pragma unroll
    for (int o = 16; o; o >>= 1) s += __shfl_xor_sync(~0u, s, o);
    float mean = s * (1.f / HID);
    float dv[4], s2 = 0.f;
#pragma unroll
    for (int u = 0; u < 4; u++) { dv[u] = h[u] - mean; float sq = dv[u] * dv[u]; s2 = s2 + sq; }
#pragma unroll
    for (int o = 16; o; o >>= 1) s2 += __shfl_xor_sync(~0u, s2, o);
    float var = s2 * (1.f / HID);
    float rstd = 1.f / sqrtf(var + 1e-5f);
#pragma unroll
    for (int u = 0; u < 4; u++) {
        int j = u * 32 + lane;
        float t = dv[u] * rstd;
        float t2 = t * __ldg(&g1[j]);
        float v = t2 + __ldg(&bt1[j]);
        gbuf[w][j] = gelu_ref(v);
    }
    __syncwarp();
    if (lane < NIN) {
        float acc = 0.f;
        for (int j = 0; j < HID; j++) acc = fmaf(gbuf[w][j], w2s[j * NIN + lane], acc);
        g_table[c * 16 + lane] = acc + __ldg(&b2[lane]);
    }
}

// ---------------- kernel 2: encoder (unchanged from R12, bit-frozen z) -------
__global__ __launch_bounds__(256) void k_enc(
    const float* __restrict__ x,
    const float* __restrict__ w1, const float* __restrict__ b1,
    const float* __restrict__ g1, const float* __restrict__ bt1,
    const float* __restrict__ w2, const float* __restrict__ b2, int N)
{
    extern __shared__ float esm[];
    float* w1s = esm;
    float* w2i = w1s + NIN * HID;
    float* gsf = w2i + HID * LAT;

    int tid = threadIdx.x;
    for (int i = tid; i < NIN * HID; i += 256) w1s[i] = w1[i];
    for (int i = tid; i < HID * LAT; i += 256) {
        int jp = i >> 7;
        int r = i & 127;
        int l = r >> 2;
        int comp = r & 3;
        int j = 2 * jp + (comp >> 1);
        int d = 2 * l + (comp & 1);
        w2i[i] = w2[j * LAT + d];
    }
    __syncthreads();

    int lane = tid & 31, w = tid >> 5;

    float b1v[4], g1v[4], btv[4];
#pragma unroll
    for (int u = 0; u < 4; u++) {
        int j = u * 32 + lane;
        b1v[u] = __ldg(&b1[j]);
        g1v[u] = __ldg(&g1[j]);
        btv[u] = __ldg(&bt1[j]);
    }
    unsigned long long b2p = pack2(__ldg(&b2[2 * lane]), __ldg(&b2[2 * lane + 1]));

    int gw = blockIdx.x * 8 + w;
    int nw = gridDim.x * 8;

    for (int t0 = gw * 8; t0 < N; t0 += nw * 8) {
#pragma unroll 1
        for (int m = 0; m < 8; m++) {
            int t = t0 + m;
            float gl0 = 0.f, gl1 = 0.f, gl2 = 0.f, gl3 = 0.f;
            if (t < N) {
                const float* xp = x + (size_t)t * NIN;
                float xv[NIN];
#pragma unroll
                for (int i = 0; i < NIN; i++) xv[i] = __ldg(&xp[i]);
                float h[4];
#pragma unroll
                for (int u = 0; u < 4; u++) {
                    float acc = 0.f;
#pragma unroll
                    for (int i = 0; i < NIN; i++) acc = fmaf(xv[i], w1s[i * HID + u * 32 + lane], acc);
                    h[u] = acc + b1v[u];
                }
                float s = (h[0] + h[1]) + (h[2] + h[3]);
#pragma unroll
                for (int o = 16; o; o >>= 1) s += __shfl_xor_sync(~0u, s, o);
                float mean = s * (1.f / HID);
                float dv[4], s2 = 0.f;
#pragma unroll
                for (int u = 0; u < 4; u++) { dv[u] = h[u] - mean; float sq = dv[u] * dv[u]; s2 = s2 + sq; }
#pragma unroll
                for (int o = 16; o; o >>= 1) s2 += __shfl_xor_sync(~0u, s2, o);
                float var = s2 * (1.f / HID);
                float rstd = 1.f / sqrtf(var + 1e-5f);
                float t1, t2, v;
                t1 = dv[0] * rstd; t2 = t1 * g1v[0]; v = t2 + btv[0]; gl0 = gelu_ref(v);
                t1 = dv[1] * rstd; t2 = t1 * g1v[1]; v = t2 + btv[1]; gl1 = gelu_ref(v);
                t1 = dv[2] * rstd; t2 = t1 * g1v[2]; v = t2 + btv[2]; gl2 = gelu_ref(v);
                t1 = dv[3] * rstd; t2 = t1 * g1v[3]; v = t2 + btv[3]; gl3 = gelu_ref(v);
            }
            float* gp = gsf + (w * 8 + m) * HID;
            gp[0 * 32 + lane] = gl0;
            gp[1 * 32 + lane] = gl1;
            gp[2 * 32 + lane] = gl2;
            gp[3 * 32 + lane] = gl3;
        }
        __syncwarp();

        unsigned long long acc[8];
#pragma unroll
        for (int m = 0; m < 8; m++) acc[m] = 0ULL;
        const float* g0 = gsf + (w * 8) * HID;
#pragma unroll 4
        for (int j = 0; j < HID; j += 2) {
            ulonglong2 wv = *(const ulonglong2*)&w2i[(j >> 1) * 128 + lane * 4];
#pragma unroll
            for (int m = 0; m < 8; m++) {
                float2 g2 = *(const float2*)&g0[m * HID + j];
                acc[m] = ffma2(pack2(g2.x, g2.x), wv.x, acc[m]);
                acc[m] = ffma2(pack2(g2.y, g2.y), wv.y, acc[m]);
            }
        }
        __syncwarp();
#pragma unroll
        for (int m = 0; m < 8; m++) {
            int t = t0 + m;
            if (t < N) g_zbuf[(size_t)t * 32 + lane] = fadd2(acc[m], b2p);
        }
    }
}

// ---------------- kernel 3: VQ — 320 threads, 2 tokens/thread, quarter-prefetch
#define GZ_ARR(arr, d) (((d) & 1) ? __uint_as_float((unsigned int)((arr)[(d) >> 1] >> 32)) \
                                  : __uint_as_float((unsigned int)(arr)[(d) >> 1]))
#define GZ_A(d) GZ_ARR(z2a, d)
#define GZ_B(d) GZ_ARR(z2b, d)

// Rescue (bit-frozen from R7): reference-replica d2 + quantization-tie force.
#define RESCUE(GETV, BIDXVAR) do {                                            \
    float zz_;                                                                \
    GPU_SUMSQ64(GETV, zz_);                                                   \
    float bestr_ = 3.4e38f, bestr2_ = 3.4e38f;                                \
    int bir_ = 0, bir2_ = 0;                                                  \
    for (int c_ = 0; c_ < CBN; c_++) {                                        \
        const float* p_ = cbs + c_ * LAT;                                     \
        float a_ = 0.f;                                                       \
        _Pragma("unroll") for (int d_ = 0; d_ < LAT; d_++)                    \
            a_ = fmaf(GETV(d_), p_[d_], a_);                                  \
        float t0_ = zz_ - 2.f * a_;                                           \
        float sc_ = t0_ + cns[c_];                                            \
        if (sc_ < bestr_) { bestr2_ = bestr_; bir2_ = bir_; bestr_ = sc_; bir_ = c_; } \
        else if (sc_ < bestr2_) { bestr2_ = sc_; bir2_ = c_; }                \
    }                                                                         \
    BIDXVAR = bir_;                                                           \
    float win_ = fabsf(bestr_) * 2.4e-7f;                                     \
    if (bestr2_ - bestr_ <= win_ && bir2_ < bir_) BIDXVAR = bir2_;            \
} while (0)

#define EPILOGUE(ARR, BIDX, T) do {                                           \
    float d2_ = 0.f;                                                          \
    const float* cr_ = cbs + (BIDX) * LAT;                                    \
    _Pragma("unroll") for (int u_ = 0; u_ < 32; u_++) {                       \
        unsigned long long zz2_ = (ARR)[u_];                                  \
        float zl_ = __uint_as_float((unsigned int)zz2_);                      \
        float zh_ = __uint_as_float((unsigned int)(zz2_ >> 32));              \
        float dl_ = zl_ - cr_[2 * u_];                                        \
        float dh_ = zh_ - cr_[2 * u_ + 1];                                    \
        d2_ = fmaf(dl_, dl_, d2_);                                            \
        d2_ = fmaf(dh_, dh_, d2_);                                            \
    }                                                                         \
    atomicAdd(&hs[BIDX], 1);                                                  \
    atomicAdd(&csum, __float2ull_rn(d2_ * 4194304.f));                        \
    if (out_idx) out_idx[T] = (float)(BIDX);                                  \
    if (out_rec) {                                                            \
        float* orp_ = out_rec + (size_t)(T) * NIN;                            \
        const float* tb_ = g_table + (BIDX) * 16;                             \
        _Pragma("unroll") for (int i_ = 0; i_ < NIN; i_++)                    \
            orp_[i_] = __ldg(&tb_[i_]);                                       \
    }                                                                         \
} while (0)

__global__ __launch_bounds__(320, 1) void k_vq(
    const float* __restrict__ cb,
    float* __restrict__ out_rec, float* __restrict__ out_idx, int N)
{
    extern __shared__ float sm[];
    float* cbs = sm;                        // 512*64 floats = 128KB
    float* cns = sm + CBN * LAT;            // 512 floats
    int* hs = (int*)(cns + CBN);            // 512 ints
    __shared__ unsigned long long csum;

    int tid = threadIdx.x;
    for (int i = tid; i < CBN * LAT; i += 320) cbs[i] = cb[i];
    for (int i = tid; i < CBN; i += 320) { cns[i] = g_cbnorm[i]; hs[i] = 0; }
    if (tid == 0) csum = 0ULL;
    __syncthreads();

    for (int base = blockIdx.x * 640; base < N; base += gridDim.x * 640) {
        int ta = base + tid;
        int tb = base + 320 + tid;
        bool va = ta < N, vb = tb < N;
        int la = va ? ta : 0;
        int lb = vb ? tb : la;

        unsigned long long z2a[32], z2b[32];
        {
            const ulonglong2* zp = (const ulonglong2*)&g_zbuf[(size_t)la * 32];
#pragma unroll
            for (int u = 0; u < 16; u++) {
                ulonglong2 v = zp[u];
                z2a[2 * u] = v.x;
                z2a[2 * u + 1] = v.y;
            }
        }
        {
            const ulonglong2* zp = (const ulonglong2*)&g_zbuf[(size_t)lb * 32];
#pragma unroll
            for (int u = 0; u < 16; u++) {
                ulonglong2 v = zp[u];
                z2b[2 * u] = v.x;
                z2b[2 * u + 1] = v.y;
            }
        }

        // ---- screen: quarter-granularity double-buffered prefetch, 2 tokens ----
        float bestA = 3.4e38f, best2A = 3.4e38f, bestB = 3.4e38f, best2B = 3.4e38f;
        int bidxA = 0, bidxB = 0;
        ulonglong2 q0[4], q1[4];
        {
            const ulonglong2* cp0 = (const ulonglong2*)cbs;
#pragma unroll
            for (int i = 0; i < 4; i++) q0[i] = cp0[i];
        }
#pragma unroll 1
        for (int c = 0; c < CBN; c++) {
            const ulonglong2* cp = (const ulonglong2*)(cbs + c * LAT);
            const ulonglong2* cpn = (const ulonglong2*)(cbs + ((c + 1) & (CBN - 1)) * LAT);
            unsigned long long aA0 = 0ULL, aA1 = 0ULL, aB0 = 0ULL, aB1 = 0ULL;
            // quarter 0 (z2[0..7]) from q0; prefetch quarter 1
#pragma unroll
            for (int i = 0; i < 4; i++) q1[i] = cp[4 + i];
            aA0 = ffma2(z2a[0], q0[0].x, aA0); aA1 = ffma2(z2a[1], q0[0].y, aA1);
            aA0 = ffma2(z2a[2], q0[1].x, aA0); aA1 = ffma2(z2a[3], q0[1].y, aA1);
            aA0 = ffma2(z2a[4], q0[2].x, aA0); aA1 = ffma2(z2a[5], q0[2].y, aA1);
            aA0 = ffma2(z2a[6], q0[3].x, aA0); aA1 = ffma2(z2a[7], q0[3].y, aA1);
            aB0 = ffma2(z2b[0], q0[0].x, aB0); aB1 = ffma2(z2b[1], q0[0].y, aB1);
            aB0 = ffma2(z2b[2], q0[1].x, aB0); aB1 = ffma2(z2b[3], q0[1].y, aB1);
            aB0 = ffma2(z2b[4], q0[2].x, aB0); aB1 = ffma2(z2b[5], q0[2].y, aB1);
            aB0 = ffma2(z2b[6], q0[3].x, aB0); aB1 = ffma2(z2b[7], q0[3].y, aB1);
            // quarter 1 (z2[8..15]) from q1; prefetch quarter 2
#pragma unroll
            for (int i = 0; i < 4; i++) q0[i] = cp[8 + i];
            aA0 = ffma2(z2a[8],  q1[0].x, aA0); aA1 = ffma2(z2a[9],  q1[0].y, aA1);
            aA0 = ffma2(z2a[10], q1[1].x, aA0); aA1 = ffma2(z2a[11], q1[1].y, aA1);
            aA0 = ffma2(z2a[12], q1[2].x, aA0); aA1 = ffma2(z2a[13], q1[2].y, aA1);
            aA0 = ffma2(z2a[14], q1[3].x, aA0); aA1 = ffma2(z2a[15], q1[3].y, aA1);
            aB0 = ffma2(z2b[8],  q1[0].x, aB0); aB1 = ffma2(z2b[9],  q1[0].y, aB1);
            aB0 = ffma2(z2b[10], q1[1].x, aB0); aB1 = ffma2(z2b[11], q1[1].y, aB1);
            aB0 = ffma2(z2b[12], q1[2].x, aB0); aB1 = ffma2(z2b[13], q1[2].y, aB1);
            aB0 = ffma2(z2b[14], q1[3].x, aB0); aB1 = ffma2(z2b[15], q1[3].y, aB1);
            // quarter 2 (z2[16..23]) from q0; prefetch quarter 3
#pragma unroll
            for (int i = 0; i < 4; i++) q1[i] = cp[12 + i];
            aA0 = ffma2(z2a[16], q0[0].x, aA0); aA1 = ffma2(z2a[17], q0[0].y, aA1);
            aA0 = ffma2(z2a[18], q0[1].x, aA0); aA1 = ffma2(z2a[19], q0[1].y, aA1);
            aA0 = ffma2(z2a[20], q0[2].x, aA0); aA1 = ffma2(z2a[21], q0[2].y, aA1);
            aA0 = ffma2(z2a[22], q0[3].x, aA0); aA1 = ffma2(z2a[23], q0[3].y, aA1);
            aB0 = ffma2(z2b[16], q0[0].x, aB0); aB1 = ffma2(z2b[17], q0[0].y, aB1);
            aB0 = ffma2(z2b[18], q0[1].x, aB0); aB1 = ffma2(z2b[19], q0[1].y, aB1);
            aB0 = ffma2(z2b[20], q0[2].x, aB0); aB1 = ffma2(z2b[21], q0[2].y, aB1);
            aB0 = ffma2(z2b[22], q0[3].x, aB0); aB1 = ffma2(z2b[23], q0[3].y, aB1);
            // quarter 3 (z2[24..31]) from q1; prefetch next code's quarter 0
#pragma unroll
            for (int i = 0; i < 4; i++) q0[i] = cpn[i];
            aA0 = ffma2(z2a[24], q1[0].x, aA0); aA1 = ffma2(z2a[25], q1[0].y, aA1);
            aA0 = ffma2(z2a[26], q1[1].x, aA0); aA1 = ffma2(z2a[27], q1[1].y, aA1);
            aA0 = ffma2(z2a[28], q1[2].x, aA0); aA1 = ffma2(z2a[29], q1[2].y, aA1);
            aA0 = ffma2(z2a[30], q1[3].x, aA0); aA1 = ffma2(z2a[31], q1[3].y, aA1);
            aB0 = ffma2(z2b[24], q1[0].x, aB0); aB1 = ffma2(z2b[25], q1[0].y, aB1);
            aB0 = ffma2(z2b[26], q1[1].x, aB0); aB1 = ffma2(z2b[27], q1[1].y, aB1);
            aB0 = ffma2(z2b[28], q1[2].x, aB0); aB1 = ffma2(z2b[29], q1[2].y, aB1);
            aB0 = ffma2(z2b[30], q1[3].x, aB0); aB1 = ffma2(z2b[31], q1[3].y, aB1);

            float cn = cns[c];
            float2 fA = unpack2(fadd2(aA0, aA1));
            float scoreA = fmaf(-2.f, fA.x + fA.y, cn);
            if (scoreA < bestA) { best2A = bestA; bestA = scoreA; bidxA = c; }
            else if (scoreA < best2A) { best2A = scoreA; }
            float2 fB = unpack2(fadd2(aB0, aB1));
            float scoreB = fmaf(-2.f, fB.x + fB.y, cn);
            if (scoreB < bestB) { best2B = bestB; bestB = scoreB; bidxB = c; }
            else if (scoreB < best2B) { best2B = scoreB; }
        }

        if (va) {
            if (best2A - bestA < 1e-4f) RESCUE(GZ_A, bidxA);
            EPILOGUE(z2a, bidxA, ta);
        }
        if (vb) {
            if (best2B - bestB < 1e-4f) RESCUE(GZ_B, bidxB);
            EPILOGUE(z2b, bidxB, tb);
        }
    }
    __syncthreads();
    for (int i = tid; i < CBN; i += 320) {
        int v = hs[i];
        if (v) atomicAdd(&g_hist[i], v);
    }
    if (tid == 0) atomicAdd(&g_commit, csum);
}

// ---------------- kernel 4: finalize scalars ----------------
__global__ void k_fin(float* out_commit, float* out_perp, int N) {
    __shared__ float red[512];
    int tid = threadIdx.x;
    float p = (float)g_hist[tid] / (float)N;
    red[tid] = p * logf(p + 1e-10f);
    __syncthreads();
    for (int s = 256; s; s >>= 1) {
        if (tid < s) red[tid] += red[tid + s];
        __syncthreads();
    }
    if (tid == 0) {
        if (out_perp) *out_perp = expf(-red[0]);
        if (out_commit) {
            double sum = (double)g_commit * (1.0 / 4194304.0);
            *out_commit = (float)(0.25 * sum / ((double)N * 64.0));
        }
    }
}

// ---------------- launch ----------------
extern "C" void kernel_launch(void* const* d_in, const int* in_sizes, int n_in,
                              void* d_out, int out_size) {
    (void)n_in;
    const float* x   = (const float*)d_in[0];
    const float* ew1 = (const float*)d_in[1];
    const float* eb1 = (const float*)d_in[2];
    const float* l1g = (const float*)d_in[3];
    const float* l1b = (const float*)d_in[4];
    const float* ew2 = (const float*)d_in[5];
    const float* eb2 = (const float*)d_in[6];
    const float* cbk = (const float*)d_in[7];
    const float* dw1 = (const float*)d_in[8];
    const float* db1 = (const float*)d_in[9];
    const float* l2g = (const float*)d_in[10];
    const float* l2b = (const float*)d_in[11];
    const float* dw2 = (const float*)d_in[12];
    const float* db2 = (const float*)d_in[13];

    int N = in_sizes[0] / NIN;
    if (N > MAXN) N = MAXN;

    float* out = (float*)d_out;
    long long rec_n = (long long)N * NIN;
    long long osz = (long long)out_size;
    float* out_rec    = (osz >= rec_n)             ? out : nullptr;
    float* out_idx    = (osz >= rec_n + N)         ? out + rec_n : nullptr;
    float* out_commit = (osz >= rec_n + N + 1)     ? out + rec_n + N : nullptr;
    float* out_perp   = (osz >= rec_n + N + 2)     ? out + rec_n + N + 1 : nullptr;

    k_init<<<1, 512>>>();
    k_dectab<<<CBN / 8, 256>>>(cbk, dw1, db1, l2g, l2b, dw2, db2);

    int smem_enc = (NIN * HID + HID * LAT + 8 * 8 * HID) * 4;  // 72704 B
    cudaFuncSetAttribute(k_enc, cudaFuncAttributeMaxDynamicSharedMemorySize, smem_enc);
    k_enc<<<444, 256, smem_enc>>>(x, ew1, eb1, l1g, l1b, ew2, eb2, N);

    int smem = CBN * LAT * 4 + CBN * 4 + CBN * 4;  // 135168 B
    cudaFuncSetAttribute(k_vq, cudaFuncAttributeMaxDynamicSharedMemorySize, smem);
    k_vq<<<148, 320, smem>>>(cbk, out_rec, out_idx, N);

    k_fin<<<1, 512>>>(out_commit, out_perp, N);
}

// round 17
// speedup vs baseline: 1.5787x; 1.2258x over previous
#include <cuda_runtime.h>
#include <math.h>

#define NIN 14
#define HID 128
#define LAT 64
#define CBN 512
#define MAXN 131072

#define SQRT2_F 1.41421356237f

// ---------------- device scratch (static: no allocations allowed) ----------------
__device__ unsigned long long g_zbuf[(size_t)MAXN * 32];  // z as f32x2 pairs, 33.5MB
__device__ float g_table[CBN * 16];                       // precomputed decoder outputs
__device__ float g_cbnorm[CBN];                           // sum(c*c), XLA:GPU warp-tree order
__device__ int g_hist[CBN];
__device__ unsigned long long g_commit;                   // fixed-point sum of ||q-z||^2

// ---------------- packed f32x2 helpers ----------------
static __device__ __forceinline__ unsigned long long ffma2(unsigned long long a,
                                                           unsigned long long b,
                                                           unsigned long long c) {
    unsigned long long d;
    asm("fma.rn.f32x2 %0, %1, %2, %3;" : "=l"(d) : "l"(a), "l"(b), "l"(c));
    return d;
}
static __device__ __forceinline__ unsigned long long fadd2(unsigned long long a,
                                                           unsigned long long b) {
    unsigned long long d;
    asm("add.rn.f32x2 %0, %1, %2;" : "=l"(d) : "l"(a), "l"(b));
    return d;
}
static __device__ __forceinline__ unsigned long long pack2(float lo, float hi) {
    unsigned long long r;
    asm("mov.b64 %0, {%1, %2};" : "=l"(r) : "r"(__float_as_uint(lo)), "r"(__float_as_uint(hi)));
    return r;
}
static __device__ __forceinline__ float2 unpack2(unsigned long long v) {
    unsigned int lo, hi;
    asm("mov.b64 {%0, %1}, %2;" : "=r"(lo), "=r"(hi) : "l"(v));
    float2 r;
    r.x = __uint_as_float(lo);
    r.y = __uint_as_float(hi);
    return r;
}

// reference-style GELU: 0.5 * x * (1 + erf(x / sqrt(2)))
static __device__ __forceinline__ float gelu_ref(float v) {
    float e = erff(v / SQRT2_F);
    return (v * (e + 1.f)) * 0.5f;
}

// XLA:GPU row-reduction emulation for 64-wide sum-of-squares (bit-frozen from R7).
#define GPU_SUMSQ64(getv, result) do {                                        \
    float _a[32];                                                             \
    _Pragma("unroll") for (int _t = 0; _t < 32; _t++) {                       \
        float _v0 = getv(_t);                                                 \
        float _v1 = getv(_t + 32);                                            \
        _a[_t] = fmaf(_v1, _v1, _v0 * _v0);                                   \
    }                                                                         \
    _Pragma("unroll") for (int _o = 16; _o >= 1; _o >>= 1)                    \
    _Pragma("unroll") for (int _t = 0; _t < 16; _t++)                         \
        if (_t < _o) _a[_t] = _a[_t] + _a[_t + _o];                           \
    result = _a[0];                                                           \
} while (0)

// ---------------- kernel 0: zero the cross-launch scratch ----------------
__global__ void k_init() {
    int t = threadIdx.x;
    if (t < CBN) g_hist[t] = 0;
    if (t == 0) g_commit = 0ULL;
}

// ---------------- kernel 1: decoder table (unchanged, bit-frozen) ----------
__global__ __launch_bounds__(256) void k_dectab(
    const float* __restrict__ cb,
    const float* __restrict__ w1, const float* __restrict__ b1,
    const float* __restrict__ g1, const float* __restrict__ bt1,
    const float* __restrict__ w2, const float* __restrict__ b2)
{
    __shared__ float w1s[LAT * HID];
    __shared__ float w2s[HID * NIN];
    __shared__ float cbuf[8][LAT];
    __shared__ float gbuf[8][HID];
    int tid = threadIdx.x;
    for (int i = tid; i < LAT * HID; i += 256) w1s[i] = w1[i];
    for (int i = tid; i < HID * NIN; i += 256) w2s[i] = w2[i];
    __syncthreads();

    int lane = tid & 31, w = tid >> 5;
    int c = blockIdx.x * 8 + w;

    for (int d = lane; d < LAT; d += 32) cbuf[w][d] = __ldg(&cb[c * LAT + d]);
    __syncwarp();

    if (lane == 0) {
        float ns;
#define GETC(d) (cbuf[w][(d)])
        GPU_SUMSQ64(GETC, ns);
#undef GETC
        g_cbnorm[c] = ns;
    }

    float h[4];
#pragma unroll
    for (int u = 0; u < 4; u++) {
        int j = u * 32 + lane;
        float acc = 0.f;
        for (int d = 0; d < LAT; d++) acc = fmaf(cbuf[w][d], w1s[d * HID + j], acc);
        h[u] = acc + __ldg(&b1[j]);
    }
    float s = (h[0] + h[1]) + (h[2] + h[3]);
#pragma unroll
    for (int o = 16; o; o >>= 1) s += __shfl_xor_sync(~0u, s, o);
    float mean = s * (1.f / HID);
    float dv[4], s2 = 0.f;
#pragma unroll
    for (int u = 0; u < 4; u++) { dv[u] = h[u] - mean; float sq = dv[u] * dv[u]; s2 = s2 + sq; }
#pragma unroll
    for (int o = 16; o; o >>= 1) s2 += __shfl_xor_sync(~0u, s2, o);
    float var = s2 * (1.f / HID);
    float rstd = 1.f / sqrtf(var + 1e-5f);
#pragma unroll
    for (int u = 0; u < 4; u++) {
        int j = u * 32 + lane;
        float t = dv[u] * rstd;
        float t2 = t * __ldg(&g1[j]);
        float v = t2 + __ldg(&bt1[j]);
        gbuf[w][j] = gelu_ref(v);
    }
    __syncwarp();
    if (lane < NIN) {
        float acc = 0.f;
        for (int j = 0; j < HID; j++) acc = fmaf(gbuf[w][j], w2s[j * NIN + lane], acc);
        g_table[c * 16 + lane] = acc + __ldg(&b2[lane]);
    }
}

// ---------------- kernel 2: encoder (unchanged from R12, bit-frozen z) -------
__global__ __launch_bounds__(256) void k_enc(
    const float* __restrict__ x,
    const float* __restrict__ w1, const float* __restrict__ b1,
    const float* __restrict__ g1, const float* __restrict__ bt1,
    const float* __restrict__ w2, const float* __restrict__ b2, int N)
{
    extern __shared__ float esm[];
    float* w1s = esm;
    float* w2i = w1s + NIN * HID;
    float* gsf = w2i + HID * LAT;

    int tid = threadIdx.x;
    for (int i = tid; i < NIN * HID; i += 256) w1s[i] = w1[i];
    for (int i = tid; i < HID * LAT; i += 256) {
        int jp = i >> 7;
        int r = i & 127;
        int l = r >> 2;
        int comp = r & 3;
        int j = 2 * jp + (comp >> 1);
        int d = 2 * l + (comp & 1);
        w2i[i] = w2[j * LAT + d];
    }
    __syncthreads();

    int lane = tid & 31, w = tid >> 5;

    float b1v[4], g1v[4], btv[4];
#pragma unroll
    for (int u = 0; u < 4; u++) {
        int j = u * 32 + lane;
        b1v[u] = __ldg(&b1[j]);
        g1v[u] = __ldg(&g1[j]);
        btv[u] = __ldg(&bt1[j]);
    }
    unsigned long long b2p = pack2(__ldg(&b2[2 * lane]), __ldg(&b2[2 * lane + 1]));

    int gw = blockIdx.x * 8 + w;
    int nw = gridDim.x * 8;

    for (int t0 = gw * 8; t0 < N; t0 += nw * 8) {
#pragma unroll 1
        for (int m = 0; m < 8; m++) {
            int t = t0 + m;
            float gl0 = 0.f, gl1 = 0.f, gl2 = 0.f, gl3 = 0.f;
            if (t < N) {
                const float* xp = x + (size_t)t * NIN;
                float xv[NIN];
#pragma unroll
                for (int i = 0; i < NIN; i++) xv[i] = __ldg(&xp[i]);
                float h[4];
#pragma unroll
                for (int u = 0; u < 4; u++) {
                    float acc = 0.f;
#pragma unroll
                    for (int i = 0; i < NIN; i++) acc = fmaf(xv[i], w1s[i * HID + u * 32 + lane], acc);
                    h[u] = acc + b1v[u];
                }
                float s = (h[0] + h[1]) + (h[2] + h[3]);
#pragma unroll
                for (int o = 16; o; o >>= 1) s += __shfl_xor_sync(~0u, s, o);
                float mean = s * (1.f / HID);
                float dv[4], s2 = 0.f;
#pragma unroll
                for (int u = 0; u < 4; u++) { dv[u] = h[u] - mean; float sq = dv[u] * dv[u]; s2 = s2 + sq; }
#pragma unroll
                for (int o = 16; o; o >>= 1) s2 += __shfl_xor_sync(~0u, s2, o);
                float var = s2 * (1.f / HID);
                float rstd = 1.f / sqrtf(var + 1e-5f);
                float t1, t2, v;
                t1 = dv[0] * rstd; t2 = t1 * g1v[0]; v = t2 + btv[0]; gl0 = gelu_ref(v);
                t1 = dv[1] * rstd; t2 = t1 * g1v[1]; v = t2 + btv[1]; gl1 = gelu_ref(v);
                t1 = dv[2] * rstd; t2 = t1 * g1v[2]; v = t2 + btv[2]; gl2 = gelu_ref(v);
                t1 = dv[3] * rstd; t2 = t1 * g1v[3]; v = t2 + btv[3]; gl3 = gelu_ref(v);
            }
            float* gp = gsf + (w * 8 + m) * HID;
            gp[0 * 32 + lane] = gl0;
            gp[1 * 32 + lane] = gl1;
            gp[2 * 32 + lane] = gl2;
            gp[3 * 32 + lane] = gl3;
        }
        __syncwarp();

        unsigned long long acc[8];
#pragma unroll
        for (int m = 0; m < 8; m++) acc[m] = 0ULL;
        const float* g0 = gsf + (w * 8) * HID;
#pragma unroll 4
        for (int j = 0; j < HID; j += 2) {
            ulonglong2 wv = *(const ulonglong2*)&w2i[(j >> 1) * 128 + lane * 4];
#pragma unroll
            for (int m = 0; m < 8; m++) {
                float2 g2 = *(const float2*)&g0[m * HID + j];
                acc[m] = ffma2(pack2(g2.x, g2.x), wv.x, acc[m]);
                acc[m] = ffma2(pack2(g2.y, g2.y), wv.y, acc[m]);
            }
        }
        __syncwarp();
#pragma unroll
        for (int m = 0; m < 8; m++) {
            int t = t0 + m;
            if (t < N) g_zbuf[(size_t)t * 32 + lane] = fadd2(acc[m], b2p);
        }
    }
}

// ---------------- kernel 3: VQ — R12 base, 2 codes per iteration -------------
#define GZ_ARR(arr, d) (((d) & 1) ? __uint_as_float((unsigned int)((arr)[(d) >> 1] >> 32)) \
                                  : __uint_as_float((unsigned int)(arr)[(d) >> 1]))
#define GZ_A(d) GZ_ARR(z2a, d)
#define GZ_B(d) GZ_ARR(z2b, d)

// Rescue (bit-frozen from R7): reference-replica d2 + quantization-tie force.
#define RESCUE(GETV, BIDXVAR) do {                                            \
    float zz_;                                                                \
    GPU_SUMSQ64(GETV, zz_);                                                   \
    float bestr_ = 3.4e38f, bestr2_ = 3.4e38f;                                \
    int bir_ = 0, bir2_ = 0;                                                  \
    for (int c_ = 0; c_ < CBN; c_++) {                                        \
        const float* p_ = cbs + c_ * LAT;                                     \
        float a_ = 0.f;                                                       \
        _Pragma("unroll") for (int d_ = 0; d_ < LAT; d_++)                    \
            a_ = fmaf(GETV(d_), p_[d_], a_);                                  \
        float t0_ = zz_ - 2.f * a_;                                           \
        float sc_ = t0_ + cns[c_];                                            \
        if (sc_ < bestr_) { bestr2_ = bestr_; bir2_ = bir_; bestr_ = sc_; bir_ = c_; } \
        else if (sc_ < bestr2_) { bestr2_ = sc_; bir2_ = c_; }                \
    }                                                                         \
    BIDXVAR = bir_;                                                           \
    float win_ = fabsf(bestr_) * 2.4e-7f;                                     \
    if (bestr2_ - bestr_ <= win_ && bir2_ < bir_) BIDXVAR = bir2_;            \
} while (0)

#define EPILOGUE(ARR, BIDX, T) do {                                           \
    float d2_ = 0.f;                                                          \
    const float* cr_ = cbs + (BIDX) * LAT;                                    \
    _Pragma("unroll") for (int u_ = 0; u_ < 32; u_++) {                       \
        unsigned long long zz2_ = (ARR)[u_];                                  \
        float zl_ = __uint_as_float((unsigned int)zz2_);                      \
        float zh_ = __uint_as_float((unsigned int)(zz2_ >> 32));              \
        float dl_ = zl_ - cr_[2 * u_];                                        \
        float dh_ = zh_ - cr_[2 * u_ + 1];                                    \
        d2_ = fmaf(dl_, dl_, d2_);                                            \
        d2_ = fmaf(dh_, dh_, d2_);                                            \
    }                                                                         \
    atomicAdd(&hs[BIDX], 1);                                                  \
    atomicAdd(&csum, __float2ull_rn(d2_ * 4194304.f));                        \
    if (out_idx) out_idx[T] = (float)(BIDX);                                  \
    if (out_rec) {                                                            \
        float* orp_ = out_rec + (size_t)(T) * NIN;                            \
        const float* tb_ = g_table + (BIDX) * 16;                             \
        _Pragma("unroll") for (int i_ = 0; i_ < NIN; i_++)                    \
            orp_[i_] = __ldg(&tb_[i_]);                                       \
    }                                                                         \
} while (0)

// half-block of FMAs: 16 dims (8 z-pairs z2x[zo..zo+3] x2? => 4 pairs) per token,
// using buffer BUF (4 ulonglong2 = dims [16*q .. 16*q+15])
#define FMA_HALF16(ACCA0, ACCA1, ACCB0, ACCB1, BUF, ZO)                       \
    ACCA0 = ffma2(z2a[(ZO) + 0], BUF[0].x, ACCA0);                            \
    ACCA1 = ffma2(z2a[(ZO) + 1], BUF[0].y, ACCA1);                            \
    ACCA0 = ffma2(z2a[(ZO) + 2], BUF[1].x, ACCA0);                            \
    ACCA1 = ffma2(z2a[(ZO) + 3], BUF[1].y, ACCA1);                            \
    ACCA0 = ffma2(z2a[(ZO) + 4], BUF[2].x, ACCA0);                            \
    ACCA1 = ffma2(z2a[(ZO) + 5], BUF[2].y, ACCA1);                            \
    ACCA0 = ffma2(z2a[(ZO) + 6], BUF[3].x, ACCA0);                            \
    ACCA1 = ffma2(z2a[(ZO) + 7], BUF[3].y, ACCA1);                            \
    ACCB0 = ffma2(z2b[(ZO) + 0], BUF[0].x, ACCB0);                            \
    ACCB1 = ffma2(z2b[(ZO) + 1], BUF[0].y, ACCB1);                            \
    ACCB0 = ffma2(z2b[(ZO) + 2], BUF[1].x, ACCB0);                            \
    ACCB1 = ffma2(z2b[(ZO) + 3], BUF[1].y, ACCB1);                            \
    ACCB0 = ffma2(z2b[(ZO) + 4], BUF[2].x, ACCB0);                            \
    ACCB1 = ffma2(z2b[(ZO) + 5], BUF[2].y, ACCB1);                            \
    ACCB0 = ffma2(z2b[(ZO) + 6], BUF[3].x, ACCB0);                            \
    ACCB1 = ffma2(z2b[(ZO) + 7], BUF[3].y, ACCB1)

__global__ __launch_bounds__(256) void k_vq(
    const float* __restrict__ cb,
    float* __restrict__ out_rec, float* __restrict__ out_idx, int N)
{
    extern __shared__ float sm[];
    float* cbs = sm;                        // 512*64 floats = 128KB
    float* cns = sm + CBN * LAT;            // 512 floats
    int* hs = (int*)(cns + CBN);            // 512 ints
    __shared__ unsigned long long csum;

    int tid = threadIdx.x;
    for (int i = tid; i < CBN * LAT; i += 256) cbs[i] = cb[i];
    for (int i = tid; i < CBN; i += 256) { cns[i] = g_cbnorm[i]; hs[i] = 0; }
    if (tid == 0) csum = 0ULL;
    __syncthreads();

    for (int base = blockIdx.x * 512; base < N; base += gridDim.x * 512) {
        int ta = base + tid;
        int tb = base + 256 + tid;
        bool va = ta < N, vb = tb < N;
        int la = va ? ta : 0;
        int lb = vb ? tb : la;

        unsigned long long z2a[32], z2b[32];
        {
            const ulonglong2* zp = (const ulonglong2*)&g_zbuf[(size_t)la * 32];
#pragma unroll
            for (int u = 0; u < 16; u++) {
                ulonglong2 v = zp[u];
                z2a[2 * u] = v.x;
                z2a[2 * u + 1] = v.y;
            }
        }
        {
            const ulonglong2* zp = (const ulonglong2*)&g_zbuf[(size_t)lb * 32];
#pragma unroll
            for (int u = 0; u < 16; u++) {
                ulonglong2 v = zp[u];
                z2b[2 * u] = v.x;
                z2b[2 * u + 1] = v.y;
            }
        }

        // ---- screen: 2 codes/iter, rotating quarter-buffers, amortized tails ----
        float bestA = 3.4e38f, best2A = 3.4e38f, bestB = 3.4e38f, best2B = 3.4e38f;
        int bidxA = 0, bidxB = 0;
        // rotating buffers: each holds a quarter-code (4 ulonglong2 = 16 dims).
        // prefetch distance = 2 quarters = 32 FMA issue slots >= LDS latency.
        ulonglong2 p0[4], p1[4], p2[4];
        {
            const ulonglong2* cp0 = (const ulonglong2*)cbs;
#pragma unroll
            for (int i = 0; i < 4; i++) p0[i] = cp0[i];       // c0 q0
#pragma unroll
            for (int i = 0; i < 4; i++) p1[i] = cp0[4 + i];   // c0 q1
        }
#pragma unroll 1
        for (int cc = 0; cc < CBN; cc += 2) {
            const ulonglong2* cp = (const ulonglong2*)(cbs + cc * LAT);       // code cc (q0..q3 at 0..15)
            const ulonglong2* cq = cp + 16;                                   // code cc+1
            const ulonglong2* cn = (const ulonglong2*)(cbs + ((cc + 2) & (CBN - 1)) * LAT);
            unsigned long long aA0 = 0ULL, aA1 = 0ULL, aB0 = 0ULL, aB1 = 0ULL;
            unsigned long long bA0 = 0ULL, bA1 = 0ULL, bB0 = 0ULL, bB1 = 0ULL;

            // code cc: quarters q0(p0), q1(p1), prefetching 2 ahead each step
#pragma unroll
            for (int i = 0; i < 4; i++) p2[i] = cp[8 + i];    // c0 q2
            FMA_HALF16(aA0, aA1, aB0, aB1, p0, 0);
#pragma unroll
            for (int i = 0; i < 4; i++) p0[i] = cp[12 + i];   // c0 q3
            FMA_HALF16(aA0, aA1, aB0, aB1, p1, 8);
#pragma unroll
            for (int i = 0; i < 4; i++) p1[i] = cq[i];        // c1 q0
            FMA_HALF16(aA0, aA1, aB0, aB1, p2, 16);
#pragma unroll
            for (int i = 0; i < 4; i++) p2[i] = cq[4 + i];    // c1 q1
            FMA_HALF16(aA0, aA1, aB0, aB1, p0, 24);
            // code cc+1: quarters
#pragma unroll
            for (int i = 0; i < 4; i++) p0[i] = cq[8 + i];    // c1 q2
            FMA_HALF16(bA0, bA1, bB0, bB1, p1, 0);
#pragma unroll
            for (int i = 0; i < 4; i++) p1[i] = cq[12 + i];   // c1 q3
            FMA_HALF16(bA0, bA1, bB0, bB1, p2, 8);
#pragma unroll
            for (int i = 0; i < 4; i++) p2[i] = cn[i];        // next c0 q0
            FMA_HALF16(bA0, bA1, bB0, bB1, p0, 16);
#pragma unroll
            for (int i = 0; i < 4; i++) p0[i] = cn[4 + i];    // next c0 q1
            FMA_HALF16(bA0, bA1, bB0, bB1, p1, 24);
            // rotate so next iteration starts with p0 = q0, p1 = q1
#pragma unroll
            for (int i = 0; i < 4; i++) { ulonglong2 t = p0[i]; p0[i] = p2[i]; p1[i] = t; }

            // ---- amortized tails: both codes' scores computed with ILP ----
            float cn0 = cns[cc], cn1 = cns[cc + 1];
            float2 fA0 = unpack2(fadd2(aA0, aA1));
            float2 fA1 = unpack2(fadd2(bA0, bA1));
            float2 fB0 = unpack2(fadd2(aB0, aB1));
            float2 fB1 = unpack2(fadd2(bB0, bB1));
            float sA0 = fmaf(-2.f, fA0.x + fA0.y, cn0);
            float sA1 = fmaf(-2.f, fA1.x + fA1.y, cn1);
            float sB0 = fmaf(-2.f, fB0.x + fB0.y, cn0);
            float sB1 = fmaf(-2.f, fB1.x + fB1.y, cn1);
            if (sA0 < bestA) { best2A = bestA; bestA = sA0; bidxA = cc; }
            else if (sA0 < best2A) { best2A = sA0; }
            if (sA1 < bestA) { best2A = bestA; bestA = sA1; bidxA = cc + 1; }
            else if (sA1 < best2A) { best2A = sA1; }
            if (sB0 < bestB) { best2B = bestB; bestB = sB0; bidxB = cc; }
            else if (sB0 < best2B) { best2B = sB0; }
            if (sB1 < bestB) { best2B = bestB; bestB = sB1; bidxB = cc + 1; }
            else if (sB1 < best2B) { best2B = sB1; }
        }

        if (va) {
            if (best2A - bestA < 1e-4f) RESCUE(GZ_A, bidxA);
            EPILOGUE(z2a, bidxA, ta);
        }
        if (vb) {
            if (best2B - bestB < 1e-4f) RESCUE(GZ_B, bidxB);
            EPILOGUE(z2b, bidxB, tb);
        }
    }
    __syncthreads();
    for (int i = tid; i < CBN; i += 256) {
        int v = hs[i];
        if (v) atomicAdd(&g_hist[i], v);
    }
    if (tid == 0) atomicAdd(&g_commit, csum);
}

// ---------------- kernel 4: finalize scalars ----------------
__global__ void k_fin(float* out_commit, float* out_perp, int N) {
    __shared__ float red[512];
    int tid = threadIdx.x;
    float p = (float)g_hist[tid] / (float)N;
    red[tid] = p * logf(p + 1e-10f);
    __syncthreads();
    for (int s = 256; s; s >>= 1) {
        if (tid < s) red[tid] += red[tid + s];
        __syncthreads();
    }
    if (tid == 0) {
        if (out_perp) *out_perp = expf(-red[0]);
        if (out_commit) {
            double sum = (double)g_commit * (1.0 / 4194304.0);
            *out_commit = (float)(0.25 * sum / ((double)N * 64.0));
        }
    }
}

// ---------------- launch ----------------
extern "C" void kernel_launch(void* const* d_in, const int* in_sizes, int n_in,
                              void* d_out, int out_size) {
    (void)n_in;
    const float* x   = (const float*)d_in[0];
    const float* ew1 = (const float*)d_in[1];
    const float* eb1 = (const float*)d_in[2];
    const float* l1g = (const float*)d_in[3];
    const float* l1b = (const float*)d_in[4];
    const float* ew2 = (const float*)d_in[5];
    const float* eb2 = (const float*)d_in[6];
    const float* cbk = (const float*)d_in[7];
    const float* dw1 = (const float*)d_in[8];
    const float* db1 = (const float*)d_in[9];
    const float* l2g = (const float*)d_in[10];
    const float* l2b = (const float*)d_in[11];
    const float* dw2 = (const float*)d_in[12];
    const float* db2 = (const float*)d_in[13];

    int N = in_sizes[0] / NIN;
    if (N > MAXN) N = MAXN;

    float* out = (float*)d_out;
    long long rec_n = (long long)N * NIN;
    long long osz = (long long)out_size;
    float* out_rec    = (osz >= rec_n)             ? out : nullptr;
    float* out_idx    = (osz >= rec_n + N)         ? out + rec_n : nullptr;
    float* out_commit = (osz >= rec_n + N + 1)     ? out + rec_n + N : nullptr;
    float* out_perp   = (osz >= rec_n + N + 2)     ? out + rec_n + N + 1 : nullptr;

    k_init<<<1, 512>>>();
    k_dectab<<<CBN / 8, 256>>>(cbk, dw1, db1, l2g, l2b, dw2, db2);

    int smem_enc = (NIN * HID + HID * LAT + 8 * 8 * HID) * 4;  // 72704 B
    cudaFuncSetAttribute(k_enc, cudaFuncAttributeMaxDynamicSharedMemorySize, smem_enc);
    k_enc<<<444, 256, smem_enc>>>(x, ew1, eb1, l1g, l1b, ew2, eb2, N);

    int smem = CBN * LAT * 4 + CBN * 4 + CBN * 4;  // 135168 B
    cudaFuncSetAttribute(k_vq, cudaFuncAttributeMaxDynamicSharedMemorySize, smem);
    k_vq<<<148, 256, smem>>>(cbk, out_rec, out_idx, N);

    k_fin<<<1, 512>>>(out_commit, out_perp, N);
}